// round 1
// baseline (speedup 1.0000x reference)
#include <cuda_runtime.h>

#define L_NODES 30000
#define JDIM 64
#define NFEAT 16
#define DEG 4

// Precomputed per-node tables: hXWt[l] = relu(X[l]@h1_w+h1_b) @ Wt, likewise Wb.
// (Wt = g1_w rows [0,64), Wb = g1_w rows [64,128).)
__device__ float g_hXWt[L_NODES * JDIM];
__device__ float g_hXWb[L_NODES * JDIM];

// ---------------------------------------------------------------------------
// Kernel 1: per node l compute hx = relu(X[l] @ h1_w + h1_b), then
//           hXWt[l] = hx @ Wt, hXWb[l] = hx @ Wb.
// Block = 256 threads = 4 nodes x 64 threads. Weights in shared.
// ---------------------------------------------------------------------------
__global__ __launch_bounds__(256) void prep_kernel(
    const float* __restrict__ X,
    const float* __restrict__ h1w,
    const float* __restrict__ h1b,
    const float* __restrict__ g1w)
{
    __shared__ float s_gw[128 * 64];   // Wt (rows 0..63) then Wb (rows 64..127)
    __shared__ float s_h1w[16 * 64];
    __shared__ float s_hx[4][64];

    int tid = threadIdx.x;
    for (int i = tid; i < 128 * 64; i += 256) s_gw[i]  = g1w[i];
    for (int i = tid; i < 16 * 64;  i += 256) s_h1w[i] = h1w[i];
    __syncthreads();

    int g = tid >> 6;
    int j = tid & 63;
    int l = blockIdx.x * 4 + g;
    if (l >= L_NODES) return;          // grid sized exactly; kept for safety

    const float* xr = X + l * NFEAT;
    float acc = h1b[j];
#pragma unroll
    for (int k = 0; k < NFEAT; k++)
        acc = fmaf(xr[k], s_h1w[k * 64 + j], acc);
    float hx = fmaxf(acc, 0.0f);
    s_hx[g][j] = hx;
    __syncthreads();

    float at = 0.0f, ab = 0.0f;
#pragma unroll
    for (int k = 0; k < 64; k++) {
        float v = s_hx[g][k];
        at = fmaf(v, s_gw[k * 64 + j],        at);
        ab = fmaf(v, s_gw[(64 + k) * 64 + j], ab);
    }
    g_hXWt[l * 64 + j] = at;
    g_hXWb[l * 64 + j] = ab;
}

// ---------------------------------------------------------------------------
// Kernel 2: per-node subset DP.
//   A[i] = hXWt[nbr_i], B[i] = hXWb[nbr_i]
//   pair  f(i,j)  = (relu(A_i+B_j+b) + relu(A_j+B_i+b)) / 2
//   PWb   = pairf @ Wb                      (6 matvecs)
//   triple f(S)   = (1/3) sum relu(A_i + PWb[S\i] + b)
//   TWb   = triplef @ Wb                    (4 matvecs)
//   quad  f       = (1/4) sum relu(A_i + TWb[i] + b)
//   E = relu(quad);  E2 = relu(hXWt[l] + E@Wb + b);  y = E2@final_w + final_b
// Block = 256 threads = 4 nodes x 64 threads. Wb column j in registers.
// ---------------------------------------------------------------------------
__global__ __launch_bounds__(256, 2) void ggcn_main_kernel(
    const int*   __restrict__ nbr,
    const float* __restrict__ g1w,
    const float* __restrict__ g1b,
    const float* __restrict__ fw,
    const float* __restrict__ fb,
    float*       __restrict__ out)
{
    __shared__ float s_buf[4][6][64];  // staging for f-vectors (broadcast source)
    __shared__ float s_e2[4][64];

    int tid = threadIdx.x;
    int g = tid >> 6;
    int j = tid & 63;
    int l = blockIdx.x * 4 + g;

    // Wb column j -> registers (read once per block from L2-resident g1_w)
    float w[64];
#pragma unroll
    for (int k = 0; k < 64; k++) w[k] = g1w[(64 + k) * 64 + j];
    float b = g1b[j];

    float A[4], Bv[4];
#pragma unroll
    for (int i = 0; i < 4; i++) {
        int n = nbr[l * 4 + i];
        A[i]  = g_hXWt[n * 64 + j];
        Bv[i] = g_hXWb[n * 64 + j];
    }
    float hxwt = g_hXWt[l * 64 + j];

    // ---- pairs ----
    const int PA[6] = {0, 0, 0, 1, 1, 2};
    const int PB[6] = {1, 2, 3, 2, 3, 3};
#pragma unroll
    for (int p = 0; p < 6; p++) {
        int i0 = PA[p], i1 = PB[p];
        float v = 0.5f * (fmaxf(A[i0] + Bv[i1] + b, 0.0f) +
                          fmaxf(A[i1] + Bv[i0] + b, 0.0f));
        s_buf[g][p][j] = v;
    }
    __syncthreads();

    float PWb[6];
#pragma unroll
    for (int p = 0; p < 6; p++) {
        float acc = 0.0f;
#pragma unroll
        for (int k = 0; k < 64; k++) acc = fmaf(s_buf[g][p][k], w[k], acc);
        PWb[p] = acc;
    }
    __syncthreads();   // protect s_buf before reuse

    // ---- triples (indexed by missing element m) ----
    const int PIDX[4][4] = {{-1, 0, 1, 2},
                            { 0,-1, 3, 4},
                            { 1, 3,-1, 5},
                            { 2, 4, 5,-1}};
#pragma unroll
    for (int m = 0; m < 4; m++) {
        float acc = 0.0f;
#pragma unroll
        for (int i = 0; i < 4; i++) {
            if (i == m) continue;
            int a = -1, c = -1;
#pragma unroll
            for (int t = 0; t < 4; t++) {
                if (t != m && t != i) { if (a < 0) a = t; else c = t; }
            }
            acc += fmaxf(A[i] + PWb[PIDX[a][c]] + b, 0.0f);
        }
        s_buf[g][m][j] = acc * (1.0f / 3.0f);
    }
    __syncthreads();

    float TWb[4];
#pragma unroll
    for (int m = 0; m < 4; m++) {
        float acc = 0.0f;
#pragma unroll
        for (int k = 0; k < 64; k++) acc = fmaf(s_buf[g][m][k], w[k], acc);
        TWb[m] = acc;
    }
    __syncthreads();   // protect s_buf before reuse

    // ---- quad + readout head ----
    float q = 0.0f;
#pragma unroll
    for (int i = 0; i < 4; i++) q += fmaxf(A[i] + TWb[i] + b, 0.0f);
    float E = fmaxf(q * 0.25f, 0.0f);
    s_buf[g][0][j] = E;
    __syncthreads();

    float acc = 0.0f;
#pragma unroll
    for (int k = 0; k < 64; k++) acc = fmaf(s_buf[g][0][k], w[k], acc);
    float E2 = fmaxf(hxwt + acc + b, 0.0f);
    s_e2[g][j] = E2;
    __syncthreads();

    if (j < 2) {
        float y = fb[j];
#pragma unroll
        for (int k = 0; k < 64; k++) y = fmaf(s_e2[g][k], fw[k * 2 + j], y);
        out[l * 2 + j] = y;
    }
}

// ---------------------------------------------------------------------------
// kernel_launch: graph-capturable, allocation-free (scratch via __device__).
// Input order per metadata: X, neighbors, h1_w, h1_b, g1_w, g1_b, final_w, final_b
// ---------------------------------------------------------------------------
extern "C" void kernel_launch(void* const* d_in, const int* in_sizes, int n_in,
                              void* d_out, int out_size)
{
    const float* X    = (const float*)d_in[0];
    const int*   nbr  = (const int*)  d_in[1];
    const float* h1w  = (const float*)d_in[2];
    const float* h1b  = (const float*)d_in[3];
    const float* g1w  = (const float*)d_in[4];
    const float* g1b  = (const float*)d_in[5];
    const float* fw   = (const float*)d_in[6];
    const float* fb   = (const float*)d_in[7];
    float* out = (float*)d_out;

    (void)in_sizes; (void)n_in; (void)out_size;

    int nblocks = (L_NODES + 3) / 4;   // 7500
    prep_kernel<<<nblocks, 256>>>(X, h1w, h1b, g1w);
    ggcn_main_kernel<<<nblocks, 256>>>(nbr, g1w, g1b, fw, fb, out);
}